// round 6
// baseline (speedup 1.0000x reference)
#include <cuda_runtime.h>
#include <cuda_bf16.h>
#include <math.h>
#include <stdint.h>

#define NN 8192
#define DD 512
#define NL 2

// ---------------- device scratch (no allocations allowed) ----------------
__device__ float          g_S   [(size_t)NN * NN];        // 256 MB scores
__device__ __nv_bfloat16  g_Phi [(size_t)NN * NN];        // 128 MB
__device__ __nv_bfloat16  g_Plo [(size_t)NN * NN];        // 128 MB
__device__ float          g_proj[(size_t)NN * 2 * DD];    // 32 MB
__device__ float          g_Xf  [(size_t)NN * DD];        // 16 MB layer-0 output
__device__ __nv_bfloat16  g_Whhi[NN * DD], g_Whlo[NN * DD];
__device__ __nv_bfloat16  g_Wshi[NN * DD], g_Wslo[NN * DD];
__device__ __nv_bfloat16  g_WhThi[NN * DD], g_WhTlo[NN * DD];   // [512, 8192]
__device__ __nv_bfloat16  g_Xhi [NN * DD], g_Xlo [NN * DD];
__device__ __nv_bfloat16  g_Wthi[NL * 2 * DD * DD], g_Wtlo[NL * 2 * DD * DD]; // [L,1024,512]

// ---------------- PTX helpers (sm_80+ baseline only) ----------------
__device__ __forceinline__ uint32_t smem_u32(const void* p) {
    uint32_t a;
    asm("{ .reg .u64 t; cvta.to.shared.u64 t, %1; cvt.u32.u64 %0, t; }" : "=r"(a) : "l"(p));
    return a;
}
#define CP16(dst, src)  asm volatile("cp.async.cg.shared.global [%0], [%1], 16;" :: "r"(dst), "l"(src))
#define CP_COMMIT()     asm volatile("cp.async.commit_group;" ::: "memory")
#define CP_WAIT0()      asm volatile("cp.async.wait_group 0;" ::: "memory")

#define LDSM4(r, a) \
    asm volatile("ldmatrix.sync.aligned.m8n8.x4.shared.b16 {%0,%1,%2,%3}, [%4];" \
        : "=r"((r)[0]), "=r"((r)[1]), "=r"((r)[2]), "=r"((r)[3]) : "r"(a))

#define MMA16816(c, a, b) \
    asm volatile("mma.sync.aligned.m16n8k16.row.col.f32.bf16.bf16.f32 " \
        "{%0,%1,%2,%3}, {%4,%5,%6,%7}, {%8,%9}, {%0,%1,%2,%3};" \
        : "+f"((c)[0]), "+f"((c)[1]), "+f"((c)[2]), "+f"((c)[3]) \
        : "r"((a)[0]), "r"((a)[1]), "r"((a)[2]), "r"((a)[3]), "r"((b)[0]), "r"((b)[1]))

__device__ __forceinline__ float lrelu(float v) { return v > 0.f ? v : 0.01f * v; }

// ---------------------------------------------------------------------------
// bf16-split GEMM on HMMA (mma.sync m16n8k16):
//   C[M,N] = sum_K (Ahi+Alo)[M,K] * (Bhi+Blo)[N,K]^T   (3 terms: A0B0+A0B1+A1B0)
// BM=BN=128, BK=32. 4 warps (2x2), warp tile 64x64 (maximal smem reuse).
// 2-stage cp.async pipeline, ONE __syncthreads per iteration, 2 CTAs/SM.
// EPI: C = leaky_relu(C + R).
// ---------------------------------------------------------------------------
#define PITCH      80
#define MAT_BYTES  (128 * PITCH)       // 10240
#define STAGE_B    (4 * MAT_BYTES)     // 40960
#define GEMM_SMEM  (2 * STAGE_B)       // 81920

template<bool EPI>
__global__ void __launch_bounds__(128, 2)
gemm_mma(const __nv_bfloat16* __restrict__ Ahi, const __nv_bfloat16* __restrict__ Alo, int lda,
         const __nv_bfloat16* __restrict__ Bhi, const __nv_bfloat16* __restrict__ Blo, int ldb,
         float* __restrict__ C, int ldc, const float* __restrict__ R, int K)
{
    extern __shared__ char smem[];
    const uint32_t sb = smem_u32(smem);
    const int tid = threadIdx.x, wid = tid >> 5, lane = tid & 31;
    const int m0 = blockIdx.y * 128, n0 = blockIdx.x * 128;
    const int wm = (wid & 1) * 64;       // warp M offset
    const int wn = (wid >> 1) * 64;      // warp N offset
    const int NC = K >> 5;               // number of BK=32 chunks

    float acc[32][4];                    // [mt*8+nt][quad]
#pragma unroll
    for (int i = 0; i < 32; i++)
#pragma unroll
        for (int q = 0; q < 4; q++) acc[i][q] = 0.f;

    // ---- load geometry: thread tid owns row tid of every matrix (4 x 16B lines each)
    const __nv_bfloat16* arow_hi = Ahi + (size_t)(m0 + tid) * lda;
    const __nv_bfloat16* arow_lo = Alo + (size_t)(m0 + tid) * lda;
    const __nv_bfloat16* brow_hi = Bhi + (size_t)(n0 + tid) * ldb;
    const __nv_bfloat16* brow_lo = Blo + (size_t)(n0 + tid) * ldb;
    const uint32_t lrow = sb + (uint32_t)tid * PITCH;

    auto load_stage = [&](int ck, int s) {
        const int k0 = ck << 5;
        const uint32_t st = lrow + (uint32_t)s * STAGE_B;
#pragma unroll
        for (int q = 0; q < 4; q++) {
            CP16(st +                 q * 16, arow_hi + k0 + q * 8);
            CP16(st +     MAT_BYTES + q * 16, arow_lo + k0 + q * 8);
            CP16(st + 2 * MAT_BYTES + q * 16, brow_hi + k0 + q * 8);
            CP16(st + 3 * MAT_BYTES + q * 16, brow_lo + k0 + q * 8);
        }
    };

    // ---- fragment lane addressing (constant across iterations)
    const uint32_t a_off = (uint32_t)(wm + (lane & 15)) * PITCH + (lane >> 4) * 16;
    // B: LDSM4 covers n-tile pair {2p, 2p+1}
    const uint32_t b_off = 2 * MAT_BYTES
        + (uint32_t)(wn + (lane & 7) + ((lane >> 4) & 1) * 8) * PITCH
        + ((lane >> 3) & 1) * 16;

    load_stage(0, 0); CP_COMMIT();

    for (int i = 0; i < NC; i++) {
        CP_WAIT0();                  // stage i resident
        __syncthreads();             // visible to all warps; all warps done with stage i-1
        if (i + 1 < NC) load_stage(i + 1, (i + 1) & 1);   // overwrites slot of stage i-1
        CP_COMMIT();

        const uint32_t st = sb + (uint32_t)(i & 1) * STAGE_B;
#pragma unroll
        for (int ks = 0; ks < 2; ks++) {
            const uint32_t kb = ks * 32;    // 16 bf16 = 32 bytes
            uint32_t b0f[4][4], b1f[4][4];  // [ntPair][4 regs]
#pragma unroll
            for (int p = 0; p < 4; p++) {
                const uint32_t bd = st + b_off + (uint32_t)p * (16 * PITCH) + kb;
                LDSM4(b0f[p], bd);
                LDSM4(b1f[p], bd + MAT_BYTES);
            }
#pragma unroll
            for (int mt = 0; mt < 4; mt++) {
                const uint32_t ad = st + a_off + (uint32_t)mt * (16 * PITCH) + kb;
                uint32_t a0f[4], a1f[4];
                LDSM4(a0f, ad);
                LDSM4(a1f, ad + MAT_BYTES);
#pragma unroll
                for (int nt = 0; nt < 8; nt++) {
                    const int bp = nt >> 1, q = (nt & 1) * 2;
                    MMA16816(acc[mt * 8 + nt], a0f, &b0f[bp][q]);
                    MMA16816(acc[mt * 8 + nt], a0f, &b1f[bp][q]);
                    MMA16816(acc[mt * 8 + nt], a1f, &b0f[bp][q]);
                }
            }
        }
    }

    // ---- epilogue
    const int rowg = lane >> 2;
    const int colp = (lane & 3) * 2;
#pragma unroll
    for (int mt = 0; mt < 4; mt++) {
#pragma unroll
        for (int nt = 0; nt < 8; nt++) {
            const int col = n0 + wn + nt * 8 + colp;
            const int r0 = m0 + wm + mt * 16 + rowg;
            const int r1 = r0 + 8;
            float* __restrict__ acc4 = acc[mt * 8 + nt];
            float2 v0 = make_float2(acc4[0], acc4[1]);
            float2 v1 = make_float2(acc4[2], acc4[3]);
            if (EPI) {
                const float2 q0 = *(const float2*)(R + (size_t)r0 * ldc + col);
                const float2 q1 = *(const float2*)(R + (size_t)r1 * ldc + col);
                v0.x = lrelu(v0.x + q0.x); v0.y = lrelu(v0.y + q0.y);
                v1.x = lrelu(v1.x + q1.x); v1.y = lrelu(v1.y + q1.y);
            }
            *(float2*)(C + (size_t)r0 * ldc + col) = v0;
            *(float2*)(C + (size_t)r1 * ldc + col) = v1;
        }
    }
}

// ---------------------------------------------------------------------------
// Row softmax * adj, output split into bf16 hi/lo.
// ---------------------------------------------------------------------------
__global__ void __launch_bounds__(256)
softmax_mask_split(const float* __restrict__ S, const float* __restrict__ adj,
                   __nv_bfloat16* __restrict__ Phi, __nv_bfloat16* __restrict__ Plo)
{
    __shared__ float row[NN];
    __shared__ float red[256];
    const int tid = threadIdx.x;
    const size_t base = (size_t)blockIdx.x * NN;

    for (int j = tid * 4; j < NN; j += 1024)
        *(float4*)&row[j] = *(const float4*)&S[base + j];
    __syncthreads();

    float m = -INFINITY;
    for (int j = tid; j < NN; j += 256) m = fmaxf(m, row[j]);
    red[tid] = m; __syncthreads();
    for (int s = 128; s > 0; s >>= 1) { if (tid < s) red[tid] = fmaxf(red[tid], red[tid + s]); __syncthreads(); }
    m = red[0]; __syncthreads();

    float l = 0.f;
    for (int j = tid; j < NN; j += 256) l += __expf(row[j] - m);
    red[tid] = l; __syncthreads();
    for (int s = 128; s > 0; s >>= 1) { if (tid < s) red[tid] += red[tid + s]; __syncthreads(); }
    const float inv = 1.0f / red[0];

    for (int j = tid * 4; j < NN; j += 1024) {
        float4 a = *(const float4*)&adj[base + j];
        float p0 = __expf(row[j + 0] - m) * inv * a.x;
        float p1 = __expf(row[j + 1] - m) * inv * a.y;
        float p2 = __expf(row[j + 2] - m) * inv * a.z;
        float p3 = __expf(row[j + 3] - m) * inv * a.w;
        __nv_bfloat16 h0 = __float2bfloat16_rn(p0), h1 = __float2bfloat16_rn(p1);
        __nv_bfloat16 h2 = __float2bfloat16_rn(p2), h3 = __float2bfloat16_rn(p3);
        __nv_bfloat16 l0 = __float2bfloat16_rn(p0 - __bfloat162float(h0));
        __nv_bfloat16 l1 = __float2bfloat16_rn(p1 - __bfloat162float(h1));
        __nv_bfloat16 l2 = __float2bfloat16_rn(p2 - __bfloat162float(h2));
        __nv_bfloat16 l3 = __float2bfloat16_rn(p3 - __bfloat162float(h3));
        __nv_bfloat162* ph = (__nv_bfloat162*)(Phi + base + j);
        __nv_bfloat162* pl = (__nv_bfloat162*)(Plo + base + j);
        ph[0] = __nv_bfloat162(h0, h1); ph[1] = __nv_bfloat162(h2, h3);
        pl[0] = __nv_bfloat162(l0, l1); pl[1] = __nv_bfloat162(l2, l3);
    }
}

// ---------------------------------------------------------------------------
// fp32 -> bf16 hi/lo split (elementwise)
// ---------------------------------------------------------------------------
__global__ void __launch_bounds__(256)
convert_split(const float* __restrict__ in, __nv_bfloat16* __restrict__ hi,
              __nv_bfloat16* __restrict__ lo, int n4)
{
    int i = blockIdx.x * blockDim.x + threadIdx.x;
    if (i >= n4) return;
    float4 x = ((const float4*)in)[i];
    __nv_bfloat16 h0 = __float2bfloat16_rn(x.x), h1 = __float2bfloat16_rn(x.y);
    __nv_bfloat16 h2 = __float2bfloat16_rn(x.z), h3 = __float2bfloat16_rn(x.w);
    __nv_bfloat162* ph = (__nv_bfloat162*)(hi) + i * 2;
    __nv_bfloat162* pl = (__nv_bfloat162*)(lo) + i * 2;
    ph[0] = __nv_bfloat162(h0, h1); ph[1] = __nv_bfloat162(h2, h3);
    pl[0] = __nv_bfloat162(__float2bfloat16_rn(x.x - __bfloat162float(h0)),
                           __float2bfloat16_rn(x.y - __bfloat162float(h1)));
    pl[1] = __nv_bfloat162(__float2bfloat16_rn(x.z - __bfloat162float(h2)),
                           __float2bfloat16_rn(x.w - __bfloat162float(h3)));
}

// ---------------------------------------------------------------------------
// split proj [8192,1024] into Wh (cols 0..511) and Ws (cols 512..1023) bf16 pairs
// ---------------------------------------------------------------------------
__global__ void __launch_bounds__(256)
proj_split(const float* __restrict__ proj,
           __nv_bfloat16* __restrict__ WhHi, __nv_bfloat16* __restrict__ WhLo,
           __nv_bfloat16* __restrict__ WsHi, __nv_bfloat16* __restrict__ WsLo)
{
    int i = blockIdx.x * blockDim.x + threadIdx.x;   // over NN*1024/4
    int rowi = i >> 8;
    int col4 = (i & 255) << 2;
    float4 x = ((const float4*)proj)[i];
    __nv_bfloat16* hi; __nv_bfloat16* lo; int off;
    if (col4 < DD) { hi = WhHi; lo = WhLo; off = rowi * DD + col4; }
    else           { hi = WsHi; lo = WsLo; off = rowi * DD + col4 - DD; }
    __nv_bfloat16 h0 = __float2bfloat16_rn(x.x), h1 = __float2bfloat16_rn(x.y);
    __nv_bfloat16 h2 = __float2bfloat16_rn(x.z), h3 = __float2bfloat16_rn(x.w);
    __nv_bfloat162* ph = (__nv_bfloat162*)(hi + off);
    __nv_bfloat162* pl = (__nv_bfloat162*)(lo + off);
    ph[0] = __nv_bfloat162(h0, h1); ph[1] = __nv_bfloat162(h2, h3);
    pl[0] = __nv_bfloat162(__float2bfloat16_rn(x.x - __bfloat162float(h0)),
                           __float2bfloat16_rn(x.y - __bfloat162float(h1)));
    pl[1] = __nv_bfloat162(__float2bfloat16_rn(x.z - __bfloat162float(h2)),
                           __float2bfloat16_rn(x.w - __bfloat162float(h3)));
}

// ---------------------------------------------------------------------------
// transpose fp32 [R,C](ldin) -> bf16 hi/lo [C,R](ldout)
// ---------------------------------------------------------------------------
__global__ void __launch_bounds__(256)
transpose_split(const float* __restrict__ in, int ldin,
                __nv_bfloat16* __restrict__ hi, __nv_bfloat16* __restrict__ lo, int ldout)
{
    __shared__ float t[32][33];
    const int tx = threadIdx.x, ty = threadIdx.y;
    const int c0 = blockIdx.x * 32, r0 = blockIdx.y * 32;
#pragma unroll
    for (int k = 0; k < 4; k++)
        t[ty + 8 * k][tx] = in[(size_t)(r0 + ty + 8 * k) * ldin + c0 + tx];
    __syncthreads();
#pragma unroll
    for (int k = 0; k < 4; k++) {
        float v = t[tx][ty + 8 * k];
        __nv_bfloat16 h = __float2bfloat16_rn(v);
        size_t o = (size_t)(c0 + ty + 8 * k) * ldout + r0 + tx;
        hi[o] = h;
        lo[o] = __float2bfloat16_rn(v - __bfloat162float(h));
    }
}

// ---------------------------------------------------------------------------
extern "C" void kernel_launch(void* const* d_in, const int* in_sizes, int n_in,
                              void* d_out, int out_size)
{
    const float* x0 = nullptr; const float* adj = nullptr; const float* W = nullptr;
    for (int i = 0; i < n_in; i++) {
        const int s = in_sizes[i];
        if      (s == NN * DD)           x0  = (const float*)d_in[i];
        else if (s == 67108864)          adj = (const float*)d_in[i];
        else if (s == NL * DD * 2 * DD)  W   = (const float*)d_in[i];
    }

    cudaFuncSetAttribute((const void*)gemm_mma<false>, cudaFuncAttributeMaxDynamicSharedMemorySize, GEMM_SMEM);
    cudaFuncSetAttribute((const void*)gemm_mma<true>,  cudaFuncAttributeMaxDynamicSharedMemorySize, GEMM_SMEM);

    float *S, *proj, *Xf;
    __nv_bfloat16 *Phi, *Plo, *Whhi, *Whlo, *Wshi, *Wslo, *WhThi, *WhTlo, *Xhi, *Xlo, *Wthi, *Wtlo;
    cudaGetSymbolAddress((void**)&S, g_S);       cudaGetSymbolAddress((void**)&proj, g_proj);
    cudaGetSymbolAddress((void**)&Xf, g_Xf);
    cudaGetSymbolAddress((void**)&Phi, g_Phi);   cudaGetSymbolAddress((void**)&Plo, g_Plo);
    cudaGetSymbolAddress((void**)&Whhi, g_Whhi); cudaGetSymbolAddress((void**)&Whlo, g_Whlo);
    cudaGetSymbolAddress((void**)&Wshi, g_Wshi); cudaGetSymbolAddress((void**)&Wslo, g_Wslo);
    cudaGetSymbolAddress((void**)&WhThi, g_WhThi); cudaGetSymbolAddress((void**)&WhTlo, g_WhTlo);
    cudaGetSymbolAddress((void**)&Xhi, g_Xhi);   cudaGetSymbolAddress((void**)&Xlo, g_Xlo);
    cudaGetSymbolAddress((void**)&Wthi, g_Wthi); cudaGetSymbolAddress((void**)&Wtlo, g_Wtlo);

    const dim3 gblk(128);
    const dim3 blk(256);
    const dim3 tblk(32, 8);

    // W^T per layer: [512,1024] -> [1024,512] bf16 pairs
    for (int l = 0; l < NL; l++)
        transpose_split<<<dim3(2 * DD / 32, DD / 32), tblk>>>(W + (size_t)l * DD * 2 * DD, 2 * DD,
                                                              Wthi + (size_t)l * 2 * DD * DD,
                                                              Wtlo + (size_t)l * 2 * DD * DD, DD);
    // x0 split
    convert_split<<<(NN * DD / 4 + 255) / 256, blk>>>(x0, Xhi, Xlo, NN * DD / 4);

    const float* xin = x0;
    for (int l = 0; l < NL; l++) {
        const __nv_bfloat16* wthi = Wthi + (size_t)l * 2 * DD * DD;
        const __nv_bfloat16* wtlo = Wtlo + (size_t)l * 2 * DD * DD;

        // proj = x @ W_l   -> [8192, 1024] fp32
        gemm_mma<false><<<dim3(2 * DD / 128, NN / 128), gblk, GEMM_SMEM>>>(
            Xhi, Xlo, DD, wthi, wtlo, DD, proj, 2 * DD, nullptr, DD);

        // split proj into Wh/Ws bf16 pairs
        proj_split<<<NN * 2 * DD / 4 / 256, blk>>>(proj, Whhi, Whlo, Wshi, Wslo);
        // WhT = transpose(proj[:, :512]) -> [512, 8192] bf16 pairs
        transpose_split<<<dim3(DD / 32, NN / 32), tblk>>>(proj, 2 * DD, WhThi, WhTlo, NN);

        // S = Wh @ Ws^T
        gemm_mma<false><<<dim3(NN / 128, NN / 128), gblk, GEMM_SMEM>>>(
            Whhi, Whlo, DD, Wshi, Wslo, DD, S, NN, nullptr, DD);

        // P = softmax(S) * adj  -> bf16 pairs
        softmax_mask_split<<<NN, blk>>>(S, adj, Phi, Plo);

        // out = leaky_relu(P @ Wh + xin)
        float* outp = (l == NL - 1) ? (float*)d_out : Xf;
        gemm_mma<true><<<dim3(DD / 128, NN / 128), gblk, GEMM_SMEM>>>(
            Phi, Plo, NN, WhThi, WhTlo, NN, outp, DD, xin, NN);

        if (l == 0) {
            convert_split<<<(NN * DD / 4 + 255) / 256, blk>>>(Xf, Xhi, Xlo, NN * DD / 4);
            xin = Xf;
        }
    }
}

// round 7
// speedup vs baseline: 1.2291x; 1.2291x over previous
#include <cuda_runtime.h>
#include <cuda_bf16.h>
#include <math.h>
#include <stdint.h>

#define NN 8192
#define DD 512
#define NL 2

// ---------------- device scratch (no allocations allowed) ----------------
__device__ float          g_S   [(size_t)NN * NN];        // 256 MB scores
__device__ __nv_bfloat16  g_Phi [(size_t)NN * NN];        // 128 MB
__device__ __nv_bfloat16  g_Plo [(size_t)NN * NN];        // 128 MB
__device__ float          g_proj[(size_t)NN * 2 * DD];    // 32 MB
__device__ float          g_Xf  [(size_t)NN * DD];        // 16 MB layer-0 output
__device__ __nv_bfloat16  g_Whhi[NN * DD], g_Whlo[NN * DD];
__device__ __nv_bfloat16  g_Wshi[NN * DD], g_Wslo[NN * DD];
__device__ __nv_bfloat16  g_WhThi[NN * DD], g_WhTlo[NN * DD];   // [512, 8192]
__device__ __nv_bfloat16  g_Xhi [NN * DD], g_Xlo [NN * DD];
__device__ __nv_bfloat16  g_Wthi[NL * 2 * DD * DD], g_Wtlo[NL * 2 * DD * DD]; // [L,1024,512]

// ---------------- PTX helpers (sm_80+ baseline only) ----------------
__device__ __forceinline__ uint32_t smem_u32(const void* p) {
    uint32_t a;
    asm("{ .reg .u64 t; cvta.to.shared.u64 t, %1; cvt.u32.u64 %0, t; }" : "=r"(a) : "l"(p));
    return a;
}
#define CP16(dst, src)  asm volatile("cp.async.cg.shared.global [%0], [%1], 16;" :: "r"(dst), "l"(src))
#define CP_COMMIT()     asm volatile("cp.async.commit_group;" ::: "memory")
#define CP_WAIT0()      asm volatile("cp.async.wait_group 0;" ::: "memory")

#define LDSM4(r, a) \
    asm volatile("ldmatrix.sync.aligned.m8n8.x4.shared.b16 {%0,%1,%2,%3}, [%4];" \
        : "=r"((r)[0]), "=r"((r)[1]), "=r"((r)[2]), "=r"((r)[3]) : "r"(a))

#define MMA16816(c, a, b) \
    asm volatile("mma.sync.aligned.m16n8k16.row.col.f32.bf16.bf16.f32 " \
        "{%0,%1,%2,%3}, {%4,%5,%6,%7}, {%8,%9}, {%0,%1,%2,%3};" \
        : "+f"((c)[0]), "+f"((c)[1]), "+f"((c)[2]), "+f"((c)[3]) \
        : "r"((a)[0]), "r"((a)[1]), "r"((a)[2]), "r"((a)[3]), "r"((b)[0]), "r"((b)[1]))

__device__ __forceinline__ float lrelu(float v) { return v > 0.f ? v : 0.01f * v; }

// ---------------------------------------------------------------------------
// bf16-split GEMM on HMMA (mma.sync m16n8k16):
//   C[M,N] = sum_K (Ahi+Alo)[M,K] * (Bhi+Blo)[N,K]^T   (3 terms: A0B0+A0B1+A1B0)
// BM=BN=128, BK=32. 8 warps (2x4), warp tile 64x32. 2-stage cp.async pipeline,
// ONE __syncthreads per iteration, 2 CTAs/SM. EPI: C = leaky_relu(C + R).
// ---------------------------------------------------------------------------
#define PITCH      80
#define MAT_BYTES  (128 * PITCH)       // 10240
#define STAGE_B    (4 * MAT_BYTES)     // 40960
#define GEMM_SMEM  (2 * STAGE_B)       // 81920

template<bool EPI>
__global__ void __launch_bounds__(256, 2)
gemm_mma(const __nv_bfloat16* __restrict__ Ahi, const __nv_bfloat16* __restrict__ Alo, int lda,
         const __nv_bfloat16* __restrict__ Bhi, const __nv_bfloat16* __restrict__ Blo, int ldb,
         float* __restrict__ C, int ldc, const float* __restrict__ R, int K)
{
    extern __shared__ char smem[];
    const uint32_t sb = smem_u32(smem);
    const int tid = threadIdx.x, wid = tid >> 5, lane = tid & 31;
    const int m0 = blockIdx.y * 128, n0 = blockIdx.x * 128;
    const int wm = (wid & 1) * 64;       // warp M offset
    const int wn = (wid >> 1) * 32;      // warp N offset
    const int NC = K >> 5;               // number of BK=32 chunks

    float acc[16][4];
#pragma unroll
    for (int i = 0; i < 16; i++)
#pragma unroll
        for (int q = 0; q < 4; q++) acc[i][q] = 0.f;

    // ---- load geometry: per matrix 512 x 16B chunks; thread loads 32B of one row
    const int lr = tid >> 1;               // row 0..127
    const int le = (tid & 1) * 16;         // element offset within BK (0 or 16)
    const uint32_t lso = (uint32_t)lr * PITCH + (tid & 1) * 32;

    auto load_stage = [&](int ck, int s) {
        const int k0 = (ck << 5) + le;
        const uint32_t st = sb + (uint32_t)s * STAGE_B + lso;
        const size_t ao = (size_t)(m0 + lr) * lda + k0;
        const size_t bo = (size_t)(n0 + lr) * ldb + k0;
        CP16(st +                 0, Ahi + ao); CP16(st +                 16, Ahi + ao + 8);
        CP16(st +     MAT_BYTES + 0, Alo + ao); CP16(st +     MAT_BYTES + 16, Alo + ao + 8);
        CP16(st + 2 * MAT_BYTES + 0, Bhi + bo); CP16(st + 2 * MAT_BYTES + 16, Bhi + bo + 8);
        CP16(st + 3 * MAT_BYTES + 0, Blo + bo); CP16(st + 3 * MAT_BYTES + 16, Blo + bo + 8);
    };

    // ---- fragment lane addressing (constant across iterations)
    const uint32_t a_off = (uint32_t)(wm + (lane & 15)) * PITCH + (lane >> 4) * 16;
    // B: ldmatrix x4 covering TWO n8 tiles
    const uint32_t b_off = 2 * MAT_BYTES
        + (uint32_t)(wn + (lane & 7) + ((lane >> 4) & 1) * 8) * PITCH
        + ((lane >> 3) & 1) * 16;

    load_stage(0, 0); CP_COMMIT();

    for (int i = 0; i < NC; i++) {
        CP_WAIT0();                  // stage i resident
        __syncthreads();             // visible; all warps also done with stage i-1
        if (i + 1 < NC) load_stage(i + 1, (i + 1) & 1);   // fills slot vacated by i-1
        CP_COMMIT();

        const uint32_t st = sb + (uint32_t)(i & 1) * STAGE_B;
#pragma unroll
        for (int ks = 0; ks < 2; ks++) {
            const uint32_t kb = ks * 32;    // 16 bf16 = 32 bytes
            uint32_t b0f[2][4], b1f[2][4];  // [ntPair][4 regs]
#pragma unroll
            for (int p = 0; p < 2; p++) {
                const uint32_t bd = st + b_off + (uint32_t)p * (16 * PITCH) + kb;
                LDSM4(b0f[p], bd);
                LDSM4(b1f[p], bd + MAT_BYTES);
            }
#pragma unroll
            for (int mt = 0; mt < 4; mt++) {
                const uint32_t ad = st + a_off + (uint32_t)mt * (16 * PITCH) + kb;
                uint32_t a0f[4], a1f[4];
                LDSM4(a0f, ad);
                LDSM4(a1f, ad + MAT_BYTES);
                // term-outer ordering: consecutive writes to the same acc are
                // separated by 3 independent MMAs (breaks the latency chain)
#pragma unroll
                for (int nt = 0; nt < 4; nt++) {
                    const int bp = nt >> 1, q = (nt & 1) * 2;
                    MMA16816(acc[mt * 4 + nt], a0f, &b0f[bp][q]);
                }
#pragma unroll
                for (int nt = 0; nt < 4; nt++) {
                    const int bp = nt >> 1, q = (nt & 1) * 2;
                    MMA16816(acc[mt * 4 + nt], a0f, &b1f[bp][q]);
                }
#pragma unroll
                for (int nt = 0; nt < 4; nt++) {
                    const int bp = nt >> 1, q = (nt & 1) * 2;
                    MMA16816(acc[mt * 4 + nt], a1f, &b0f[bp][q]);
                }
            }
        }
    }

    // ---- epilogue
    const int rowg = lane >> 2;
    const int colp = (lane & 3) * 2;
#pragma unroll
    for (int mt = 0; mt < 4; mt++) {
#pragma unroll
        for (int nt = 0; nt < 4; nt++) {
            const int col = n0 + wn + nt * 8 + colp;
            const int r0 = m0 + wm + mt * 16 + rowg;
            const int r1 = r0 + 8;
            float* __restrict__ acc4 = acc[mt * 4 + nt];
            float2 v0 = make_float2(acc4[0], acc4[1]);
            float2 v1 = make_float2(acc4[2], acc4[3]);
            if (EPI) {
                const float2 q0 = *(const float2*)(R + (size_t)r0 * ldc + col);
                const float2 q1 = *(const float2*)(R + (size_t)r1 * ldc + col);
                v0.x = lrelu(v0.x + q0.x); v0.y = lrelu(v0.y + q0.y);
                v1.x = lrelu(v1.x + q1.x); v1.y = lrelu(v1.y + q1.y);
            }
            *(float2*)(C + (size_t)r0 * ldc + col) = v0;
            *(float2*)(C + (size_t)r1 * ldc + col) = v1;
        }
    }
}

// ---------------------------------------------------------------------------
// Row softmax * adj, output split into bf16 hi/lo.
// ---------------------------------------------------------------------------
__global__ void __launch_bounds__(256)
softmax_mask_split(const float* __restrict__ S, const float* __restrict__ adj,
                   __nv_bfloat16* __restrict__ Phi, __nv_bfloat16* __restrict__ Plo)
{
    __shared__ float row[NN];
    __shared__ float red[256];
    const int tid = threadIdx.x;
    const size_t base = (size_t)blockIdx.x * NN;

    for (int j = tid * 4; j < NN; j += 1024)
        *(float4*)&row[j] = *(const float4*)&S[base + j];
    __syncthreads();

    float m = -INFINITY;
    for (int j = tid; j < NN; j += 256) m = fmaxf(m, row[j]);
    red[tid] = m; __syncthreads();
    for (int s = 128; s > 0; s >>= 1) { if (tid < s) red[tid] = fmaxf(red[tid], red[tid + s]); __syncthreads(); }
    m = red[0]; __syncthreads();

    float l = 0.f;
    for (int j = tid; j < NN; j += 256) l += __expf(row[j] - m);
    red[tid] = l; __syncthreads();
    for (int s = 128; s > 0; s >>= 1) { if (tid < s) red[tid] += red[tid + s]; __syncthreads(); }
    const float inv = 1.0f / red[0];

    for (int j = tid * 4; j < NN; j += 1024) {
        float4 a = *(const float4*)&adj[base + j];
        float p0 = __expf(row[j + 0] - m) * inv * a.x;
        float p1 = __expf(row[j + 1] - m) * inv * a.y;
        float p2 = __expf(row[j + 2] - m) * inv * a.z;
        float p3 = __expf(row[j + 3] - m) * inv * a.w;
        __nv_bfloat16 h0 = __float2bfloat16_rn(p0), h1 = __float2bfloat16_rn(p1);
        __nv_bfloat16 h2 = __float2bfloat16_rn(p2), h3 = __float2bfloat16_rn(p3);
        __nv_bfloat16 l0 = __float2bfloat16_rn(p0 - __bfloat162float(h0));
        __nv_bfloat16 l1 = __float2bfloat16_rn(p1 - __bfloat162float(h1));
        __nv_bfloat16 l2 = __float2bfloat16_rn(p2 - __bfloat162float(h2));
        __nv_bfloat16 l3 = __float2bfloat16_rn(p3 - __bfloat162float(h3));
        __nv_bfloat162* ph = (__nv_bfloat162*)(Phi + base + j);
        __nv_bfloat162* pl = (__nv_bfloat162*)(Plo + base + j);
        ph[0] = __nv_bfloat162(h0, h1); ph[1] = __nv_bfloat162(h2, h3);
        pl[0] = __nv_bfloat162(l0, l1); pl[1] = __nv_bfloat162(l2, l3);
    }
}

// ---------------------------------------------------------------------------
// fp32 -> bf16 hi/lo split (elementwise)
// ---------------------------------------------------------------------------
__global__ void __launch_bounds__(256)
convert_split(const float* __restrict__ in, __nv_bfloat16* __restrict__ hi,
              __nv_bfloat16* __restrict__ lo, int n4)
{
    int i = blockIdx.x * blockDim.x + threadIdx.x;
    if (i >= n4) return;
    float4 x = ((const float4*)in)[i];
    __nv_bfloat16 h0 = __float2bfloat16_rn(x.x), h1 = __float2bfloat16_rn(x.y);
    __nv_bfloat16 h2 = __float2bfloat16_rn(x.z), h3 = __float2bfloat16_rn(x.w);
    __nv_bfloat162* ph = (__nv_bfloat162*)(hi) + i * 2;
    __nv_bfloat162* pl = (__nv_bfloat162*)(lo) + i * 2;
    ph[0] = __nv_bfloat162(h0, h1); ph[1] = __nv_bfloat162(h2, h3);
    pl[0] = __nv_bfloat162(__float2bfloat16_rn(x.x - __bfloat162float(h0)),
                           __float2bfloat16_rn(x.y - __bfloat162float(h1)));
    pl[1] = __nv_bfloat162(__float2bfloat16_rn(x.z - __bfloat162float(h2)),
                           __float2bfloat16_rn(x.w - __bfloat162float(h3)));
}

// ---------------------------------------------------------------------------
// split proj [8192,1024] into Wh (cols 0..511) and Ws (cols 512..1023) bf16 pairs
// ---------------------------------------------------------------------------
__global__ void __launch_bounds__(256)
proj_split(const float* __restrict__ proj,
           __nv_bfloat16* __restrict__ WhHi, __nv_bfloat16* __restrict__ WhLo,
           __nv_bfloat16* __restrict__ WsHi, __nv_bfloat16* __restrict__ WsLo)
{
    int i = blockIdx.x * blockDim.x + threadIdx.x;   // over NN*1024/4
    int rowi = i >> 8;
    int col4 = (i & 255) << 2;
    float4 x = ((const float4*)proj)[i];
    __nv_bfloat16* hi; __nv_bfloat16* lo; int off;
    if (col4 < DD) { hi = WhHi; lo = WhLo; off = rowi * DD + col4; }
    else           { hi = WsHi; lo = WsLo; off = rowi * DD + col4 - DD; }
    __nv_bfloat16 h0 = __float2bfloat16_rn(x.x), h1 = __float2bfloat16_rn(x.y);
    __nv_bfloat16 h2 = __float2bfloat16_rn(x.z), h3 = __float2bfloat16_rn(x.w);
    __nv_bfloat162* ph = (__nv_bfloat162*)(hi + off);
    __nv_bfloat162* pl = (__nv_bfloat162*)(lo + off);
    ph[0] = __nv_bfloat162(h0, h1); ph[1] = __nv_bfloat162(h2, h3);
    pl[0] = __nv_bfloat162(__float2bfloat16_rn(x.x - __bfloat162float(h0)),
                           __float2bfloat16_rn(x.y - __bfloat162float(h1)));
    pl[1] = __nv_bfloat162(__float2bfloat16_rn(x.z - __bfloat162float(h2)),
                           __float2bfloat16_rn(x.w - __bfloat162float(h3)));
}

// ---------------------------------------------------------------------------
// transpose fp32 [R,C](ldin) -> bf16 hi/lo [C,R](ldout)
// ---------------------------------------------------------------------------
__global__ void __launch_bounds__(256)
transpose_split(const float* __restrict__ in, int ldin,
                __nv_bfloat16* __restrict__ hi, __nv_bfloat16* __restrict__ lo, int ldout)
{
    __shared__ float t[32][33];
    const int tx = threadIdx.x, ty = threadIdx.y;
    const int c0 = blockIdx.x * 32, r0 = blockIdx.y * 32;
#pragma unroll
    for (int k = 0; k < 4; k++)
        t[ty + 8 * k][tx] = in[(size_t)(r0 + ty + 8 * k) * ldin + c0 + tx];
    __syncthreads();
#pragma unroll
    for (int k = 0; k < 4; k++) {
        float v = t[tx][ty + 8 * k];
        __nv_bfloat16 h = __float2bfloat16_rn(v);
        size_t o = (size_t)(c0 + ty + 8 * k) * ldout + r0 + tx;
        hi[o] = h;
        lo[o] = __float2bfloat16_rn(v - __bfloat162float(h));
    }
}

// ---------------------------------------------------------------------------
extern "C" void kernel_launch(void* const* d_in, const int* in_sizes, int n_in,
                              void* d_out, int out_size)
{
    const float* x0 = nullptr; const float* adj = nullptr; const float* W = nullptr;
    for (int i = 0; i < n_in; i++) {
        const int s = in_sizes[i];
        if      (s == NN * DD)           x0  = (const float*)d_in[i];
        else if (s == 67108864)          adj = (const float*)d_in[i];
        else if (s == NL * DD * 2 * DD)  W   = (const float*)d_in[i];
    }

    cudaFuncSetAttribute((const void*)gemm_mma<false>, cudaFuncAttributeMaxDynamicSharedMemorySize, GEMM_SMEM);
    cudaFuncSetAttribute((const void*)gemm_mma<true>,  cudaFuncAttributeMaxDynamicSharedMemorySize, GEMM_SMEM);

    float *S, *proj, *Xf;
    __nv_bfloat16 *Phi, *Plo, *Whhi, *Whlo, *Wshi, *Wslo, *WhThi, *WhTlo, *Xhi, *Xlo, *Wthi, *Wtlo;
    cudaGetSymbolAddress((void**)&S, g_S);       cudaGetSymbolAddress((void**)&proj, g_proj);
    cudaGetSymbolAddress((void**)&Xf, g_Xf);
    cudaGetSymbolAddress((void**)&Phi, g_Phi);   cudaGetSymbolAddress((void**)&Plo, g_Plo);
    cudaGetSymbolAddress((void**)&Whhi, g_Whhi); cudaGetSymbolAddress((void**)&Whlo, g_Whlo);
    cudaGetSymbolAddress((void**)&Wshi, g_Wshi); cudaGetSymbolAddress((void**)&Wslo, g_Wslo);
    cudaGetSymbolAddress((void**)&WhThi, g_WhThi); cudaGetSymbolAddress((void**)&WhTlo, g_WhTlo);
    cudaGetSymbolAddress((void**)&Xhi, g_Xhi);   cudaGetSymbolAddress((void**)&Xlo, g_Xlo);
    cudaGetSymbolAddress((void**)&Wthi, g_Wthi); cudaGetSymbolAddress((void**)&Wtlo, g_Wtlo);

    const dim3 blk(256);
    const dim3 tblk(32, 8);

    // W^T per layer: [512,1024] -> [1024,512] bf16 pairs
    for (int l = 0; l < NL; l++)
        transpose_split<<<dim3(2 * DD / 32, DD / 32), tblk>>>(W + (size_t)l * DD * 2 * DD, 2 * DD,
                                                              Wthi + (size_t)l * 2 * DD * DD,
                                                              Wtlo + (size_t)l * 2 * DD * DD, DD);
    // x0 split
    convert_split<<<(NN * DD / 4 + 255) / 256, blk>>>(x0, Xhi, Xlo, NN * DD / 4);

    const float* xin = x0;
    for (int l = 0; l < NL; l++) {
        const __nv_bfloat16* wthi = Wthi + (size_t)l * 2 * DD * DD;
        const __nv_bfloat16* wtlo = Wtlo + (size_t)l * 2 * DD * DD;

        // proj = x @ W_l   -> [8192, 1024] fp32
        gemm_mma<false><<<dim3(2 * DD / 128, NN / 128), blk, GEMM_SMEM>>>(
            Xhi, Xlo, DD, wthi, wtlo, DD, proj, 2 * DD, nullptr, DD);

        // split proj into Wh/Ws bf16 pairs
        proj_split<<<NN * 2 * DD / 4 / 256, blk>>>(proj, Whhi, Whlo, Wshi, Wslo);
        // WhT = transpose(proj[:, :512]) -> [512, 8192] bf16 pairs
        transpose_split<<<dim3(DD / 32, NN / 32), tblk>>>(proj, 2 * DD, WhThi, WhTlo, NN);

        // S = Wh @ Ws^T
        gemm_mma<false><<<dim3(NN / 128, NN / 128), blk, GEMM_SMEM>>>(
            Whhi, Whlo, DD, Wshi, Wslo, DD, S, NN, nullptr, DD);

        // P = softmax(S) * adj  -> bf16 pairs
        softmax_mask_split<<<NN, blk>>>(S, adj, Phi, Plo);

        // out = leaky_relu(P @ Wh + xin)
        float* outp = (l == NL - 1) ? (float*)d_out : Xf;
        gemm_mma<true><<<dim3(DD / 128, NN / 128), blk, GEMM_SMEM>>>(
            Phi, Plo, NN, WhThi, WhTlo, NN, outp, DD, xin, NN);

        if (l == 0) {
            convert_split<<<(NN * DD / 4 + 255) / 256, blk>>>(Xf, Xhi, Xlo, NN * DD / 4);
            xin = Xf;
        }
    }
}